// round 4
// baseline (speedup 1.0000x reference)
#include <cuda_runtime.h>

#define BATCH 16
#define CH    64
#define HH    256
#define WW    256
#define M2    20
#define NRR   40
#define NIMG  (BATCH*CH)     /* 1024  */
#define NROW  (NIMG*HH)      /* 262144 */

// ---------------- scratch (device globals; no allocation allowed) ----------
__device__ float2 g_tw[256];          // e^{+2*pi*i*t/256}
__device__ float2 g_Y[NROW*M2];       // forward-W result  [img*256+h][k2]   (~42MB)
__device__ float2 g_X[NIMG*NRR*M2];   // forward modes     [img][r][k2]      (~6.5MB)
__device__ float2 g_O[NIMG*NRR*M2];   // mixed modes
__device__ float2 g_Z[NROW*M2];       // inverse-H result  [img*256+h][k2]   (~42MB)

__global__ void init_tw() {
    int t = threadIdx.x;
    double a = 6.283185307179586476925286766559 * (double)t / 256.0;
    g_tw[t] = make_float2((float)cos(a), (float)sin(a));
}

// ---------------- stage 1: partial rfft along W ----------------------------
// Y[row][k2] = sum_w x[row][w] e^{-2pi i k2 w/256}, k2<20
// Real-input fold: Re = x0 + (-1)^k2 x128 + sum_{w=1..127} (x_w+x_{256-w}) cos(w*th)
//                  Im = -sum_{w=1..127} (x_w-x_{256-w}) sin(w*th)
// Each thread handles rows r and r+8 sharing one twiddle recurrence.
__global__ __launch_bounds__(160) void fwdW(const float* __restrict__ x) {
    __shared__ float  xs[16*256];     // 16KB
    __shared__ float2 seo[16*129];    // padded: rows 1032B apart (kills bank conflict)
    int t = threadIdx.x;
    const float4* xg = (const float4*)(x + (size_t)blockIdx.x * 4096);
    for (int i = t; i < 1024; i += 160) ((float4*)xs)[i] = xg[i];
    __syncthreads();
    for (int i = t; i < 16*127; i += 160) {
        int r = i / 127, w = 1 + (i - r*127);
        float a = xs[r*256 + w], b = xs[r*256 + 256 - w];
        seo[r*129 + w] = make_float2(a + b, a - b);
    }
    __syncthreads();
    int r = t / 20, k2 = t - 20*(t/20);
    float2 tw = g_tw[k2];
    float c1 = tw.x, s1 = tw.y;          // step e^{+i th}, th = 2pi k2/256
    float c = c1, s = s1;
    float ar0 = 0.f, ai0 = 0.f, ar1 = 0.f, ai1 = 0.f;
    const float2* p0 = &seo[r*129];
    const float2* p1 = &seo[(r + 8)*129];
    for (int w = 1; w < 128; ++w) {
        float2 e0 = p0[w], e1 = p1[w];
        ar0 = fmaf(e0.x, c, ar0);  ai0 = fmaf(e0.y, s, ai0);
        ar1 = fmaf(e1.x, c, ar1);  ai1 = fmaf(e1.y, s, ai1);
        float cn = fmaf(c, c1, -(s*s1));
        s = fmaf(s, c1, c*s1);
        c = cn;
    }
    {
        float x0 = xs[r*256], xm = xs[r*256 + 128];
        float re = ar0 + x0 + ((k2 & 1) ? -xm : xm);
        g_Y[((size_t)blockIdx.x*16 + r)*20 + k2] = make_float2(re, -ai0);
    }
    {
        float x0 = xs[(r + 8)*256], xm = xs[(r + 8)*256 + 128];
        float re = ar1 + x0 + ((k2 & 1) ? -xm : xm);
        g_Y[((size_t)blockIdx.x*16 + r + 8)*20 + k2] = make_float2(re, -ai1);
    }
}

// ---------------- stage 2: partial complex DFT along H ---------------------
// X[r][k2] = sum_h Y[h][k2] e^{-2pi i k1_r h/256}, k1_r = r<20 ? r : 216+r
// Each thread handles k2 and k2+10 sharing one k1 recurrence.
__global__ __launch_bounds__(512) void fwdH() {
    __shared__ float2 Ys[HH*M2];   // 40KB
    int t = threadIdx.x, img = blockIdx.x;
    const float2* src = &g_Y[(size_t)img * HH * M2];
    for (int i = t; i < HH*M2; i += 512) Ys[i] = src[i];
    __syncthreads();
    if (t >= 400) return;
    int r = t / 10, k2 = t - 10*(t/10);
    int k1 = r + (r >= 20 ? 216 : 0);
    float2 tw = g_tw[k1];
    float c1 = tw.x, s1 = -tw.y;          // step e^{-i th}
    float c = 1.f, s = 0.f;
    float Xr0 = 0.f, Xi0 = 0.f, Xr1 = 0.f, Xi1 = 0.f;
    for (int h = 0; h < HH; ++h) {
        float2 y0 = Ys[h*20 + k2];
        float2 y1 = Ys[h*20 + k2 + 10];
        Xr0 = fmaf(y0.x, c, Xr0);  Xr0 = fmaf(-y0.y, s, Xr0);
        Xi0 = fmaf(y0.y, c, Xi0);  Xi0 = fmaf(y0.x, s, Xi0);
        Xr1 = fmaf(y1.x, c, Xr1);  Xr1 = fmaf(-y1.y, s, Xr1);
        Xi1 = fmaf(y1.y, c, Xi1);  Xi1 = fmaf(y1.x, s, Xi1);
        float cn = fmaf(c, c1, -(s*s1));
        s = fmaf(s, c1, c*s1);
        c = cn;
    }
    g_X[(size_t)img*800 + r*20 + k2]      = make_float2(Xr0, Xi0);
    g_X[(size_t)img*800 + r*20 + k2 + 10] = make_float2(Xr1, Xi1);
}

// ---------------- stage 3: per-mode complex channel mixing -----------------
// O[b][o][mode] = sum_i X[b][i][mode] * W[i][o][mode]  (complex)
__global__ __launch_bounds__(256) void mixk(const float* __restrict__ w1r, const float* __restrict__ w1i,
                                            const float* __restrict__ w2r, const float* __restrict__ w2i) {
    __shared__ float2 Xs[1024];   // [b*64+i]
    __shared__ float2 Ws[4096];   // [i*64+o]
    int t = threadIdx.x, mo = blockIdx.x;
    int r = mo / 20, k2 = mo - 20*r;
    const float *wr, *wi; int m1;
    if (r < 20) { wr = w1r; wi = w1i; m1 = r; } else { wr = w2r; wi = w2i; m1 = r - 20; }
    int off = m1*20 + k2;
    for (int u = t; u < 1024; u += 256) Xs[u] = g_X[(size_t)u*800 + mo];
    for (int u = t; u < 4096; u += 256) Ws[u] = make_float2(wr[u*400 + off], wi[u*400 + off]);
    __syncthreads();
    for (int j = 0; j < 4; ++j) {
        int u = t + 256*j, b = u >> 6, o = u & 63;
        float ar = 0.f, ai = 0.f;
        #pragma unroll 8
        for (int i = 0; i < 64; ++i) {
            float2 X = Xs[b*64 + i]; float2 Wv = Ws[i*64 + o];
            ar = fmaf(X.x, Wv.x, ar);  ar = fmaf(-X.y, Wv.y, ar);
            ai = fmaf(X.x, Wv.y, ai);  ai = fmaf(X.y, Wv.x, ai);
        }
        g_O[(size_t)u*800 + mo] = make_float2(ar, ai);
    }
}

// ---------------- stage 4: inverse DFT along H -----------------------------
// Z[h][k2] = sum_r O[r][k2] e^{+2pi i k1_r h/256}   (no 1/H yet)
__global__ __launch_bounds__(256) void invH() {
    __shared__ float2 Os[800];
    __shared__ float2 Zst[HH*M2];   // 40KB staging for coalesced store
    int t = threadIdx.x, img = blockIdx.x;
    const float2* src = &g_O[(size_t)img*800];
    for (int i = t; i < 800; i += 256) Os[i] = src[i];
    __syncthreads();
    int h = t;
    float2 tw = g_tw[h];
    float ch = tw.x, sh = tw.y;   // step e^{+i phi}, phi = 2pi h/256
    float Zr[20], Zi[20];
    #pragma unroll
    for (int k = 0; k < 20; ++k) { Zr[k] = 0.f; Zi[k] = 0.f; }
    float c = 1.f, s = 0.f;
    for (int rr = 0; rr < 20; ++rr) {              // k1 = 0..19
        #pragma unroll
        for (int k = 0; k < 20; ++k) {
            float2 O = Os[rr*20 + k];
            Zr[k] = fmaf(O.x, c, Zr[k]);  Zr[k] = fmaf(-O.y, s, Zr[k]);
            Zi[k] = fmaf(O.y, c, Zi[k]);  Zi[k] = fmaf(O.x, s, Zi[k]);
        }
        float cn = fmaf(c, ch, -(s*sh)); s = fmaf(s, ch, c*sh); c = cn;
    }
    float c2 = c, s2 = -s;                          // e^{-i*20 phi} == k1 = 236
    for (int rr = 20; rr < 40; ++rr) {             // k1 = 236..255
        #pragma unroll
        for (int k = 0; k < 20; ++k) {
            float2 O = Os[rr*20 + k];
            Zr[k] = fmaf(O.x, c2, Zr[k]);  Zr[k] = fmaf(-O.y, s2, Zr[k]);
            Zi[k] = fmaf(O.y, c2, Zi[k]);  Zi[k] = fmaf(O.x, s2, Zi[k]);
        }
        float cn = fmaf(c2, ch, -(s2*sh)); s2 = fmaf(s2, ch, c2*sh); c2 = cn;
    }
    #pragma unroll
    for (int k = 0; k < 20; ++k) Zst[h*20 + k] = make_float2(Zr[k], Zi[k]);
    __syncthreads();
    float2* dst = &g_Z[(size_t)img * HH * M2];
    for (int i = t; i < HH*M2; i += 256) dst[i] = Zst[i];
}

// ---------------- stage 5: inverse real DFT along W ------------------------
// out[w]     = (ReZ0 + 2*sum_{k=1..19}(ReZ c - ImZ s)) / 65536
// out[256-w] = (ReZ0 + 2*sum_{k=1..19}(ReZ c + ImZ s)) / 65536
__global__ __launch_bounds__(256) void invW(float* __restrict__ out) {
    __shared__ float2 Zs[40];
    int t = threadIdx.x;
    for (int i = t; i < 40; i += 256) Zs[i] = g_Z[(size_t)blockIdx.x*40 + i];
    __syncthreads();
    int rl = t >> 7, wl = t & 127;
    const float2* z = &Zs[rl*20];
    float base = z[0].x;                 // Im of DC bin ignored (Hermitian semantics)
    float2 tw = g_tw[wl];
    float cw = tw.x, sw = tw.y, c = cw, s = sw, A = 0.f, Bs = 0.f;
    #pragma unroll
    for (int k = 1; k < 20; ++k) {
        float2 Z = z[k];
        A  = fmaf(Z.x, c, A);
        Bs = fmaf(Z.y, s, Bs);
        float cn = fmaf(c, cw, -(s*sw)); s = fmaf(s, cw, c*sw); c = cn;
    }
    const float SC = 1.f / 65536.f;
    size_t Rg = (size_t)blockIdx.x*2 + rl;
    float* orow = out + Rg*256;
    orow[wl] = (base + 2.f*(A - Bs)) * SC;
    if (wl) {
        orow[256 - wl] = (base + 2.f*(A + Bs)) * SC;
    } else {
        float acc = 0.f, sg = -1.f;      // w = 128: cos(pi k) = (-1)^k, sin = 0
        #pragma unroll
        for (int k = 1; k < 20; ++k) { acc = fmaf(sg, z[k].x, acc); sg = -sg; }
        orow[128] = (base + 2.f*acc) * SC;
    }
}

extern "C" void kernel_launch(void* const* d_in, const int* in_sizes, int n_in,
                              void* d_out, int out_size) {
    const float* x   = (const float*)d_in[0];
    const float* w1r = (const float*)d_in[1];
    const float* w1i = (const float*)d_in[2];
    const float* w2r = (const float*)d_in[3];
    const float* w2i = (const float*)d_in[4];
    float* out = (float*)d_out;

    init_tw<<<1, 256>>>();
    fwdW<<<NROW/16, 160>>>(x);
    fwdH<<<NIMG, 512>>>();
    mixk<<<NRR*M2, 256>>>(w1r, w1i, w2r, w2i);
    invH<<<NIMG, 256>>>();
    invW<<<NROW/2, 256>>>(out);
}